// round 11
// baseline (speedup 1.0000x reference)
#include <cuda_runtime.h>
#include <cuda_bf16.h>
#include <math.h>

#define NN   20000
#define FIN  128
#define HID  32
#define HEADS 8
#define HC   256
#define EE   320000
#define ETOT 340000
#define GG   64
#define CLS  10

// ---------------- scratch (static device globals; no allocation) ----------------
__device__ __align__(16) float g_h[NN * HC];
__device__ __align__(16) float g_x1[NN * HC];
__device__ __align__(16) float g_out2[NN * HC];
__device__ float    g_al[NN * HEADS];
__device__ float    g_ar[NN * HEADS];
__device__ __align__(16) int g_deg[NN];
__device__ int      g_cursor[NN];
__device__ int      g_rowptr[NN + 1];
__device__ int      g_srcs[ETOT];
__device__ float    g_sums[GG * HC];
__device__ int      g_cnt[GG];
__device__ int      g_is64;

// ---------------- helpers ----------------
__device__ __forceinline__ int idx_at(const void* p, int i) {
    if (g_is64) return (int)((const long long*)p)[i];
    return ((const int*)p)[i];
}
__device__ __forceinline__ void edge_sd(const void* ei, int e, int& s, int& d) {
    if (e < EE) { s = idx_at(ei, e); d = idx_at(ei, EE + e); }
    else        { s = e - EE; d = e - EE; }
}
__device__ __forceinline__ int edge_dst(const void* ei, int e) {
    return (e < EE) ? idx_at(ei, EE + e) : (e - EE);
}

// ---------------- zero + dtype detect (fused) ----------------
// Index values are < 20000 < 2^31: genuine int64 => every high word is 0.
__global__ void init_kernel(const void* ei) {
    int i = blockIdx.x * blockDim.x + threadIdx.x;
    if (i < NN) { g_deg[i] = 0; g_cursor[i] = 0; }
    if (blockIdx.x == 0 && threadIdx.x == 0) {
        const int* p = (const int*)ei;
        int or_hi = 0;
        #pragma unroll
        for (int k = 0; k < 64; k++) or_hi |= p[2 * k + 1];
        g_is64 = (or_hi == 0) ? 1 : 0;
    }
}

// ---------------- CSR build ----------------
__global__ void degree_kernel(const void* __restrict__ ei) {
    int e = blockIdx.x * blockDim.x + threadIdx.x;
    if (e >= ETOT) return;
    atomicAdd(&g_deg[edge_dst(ei, e)], 1);
}

// shfl-based scan: 1024 threads x 20 items, int4 loads
__global__ void scan_kernel() {
    __shared__ int warp_sums[32];
    const int CH = 20;
    int t = threadIdx.x;
    int lane = t & 31, w = t >> 5;
    int base = t * CH;
    int local[CH];
    #pragma unroll
    for (int i = 0; i < CH / 4; i++) {
        int4 v4 = ((const int4*)g_deg)[(base >> 2) + i];
        local[4 * i + 0] = v4.x; local[4 * i + 1] = v4.y;
        local[4 * i + 2] = v4.z; local[4 * i + 3] = v4.w;
    }
    int s = 0;
    #pragma unroll
    for (int i = 0; i < CH; i++) { int v = local[i]; local[i] = s; s += v; }
    int ss = s;
    #pragma unroll
    for (int o = 1; o < 32; o <<= 1) {
        int vv = __shfl_up_sync(0xffffffffu, ss, o);
        if (lane >= o) ss += vv;
    }
    if (lane == 31) warp_sums[w] = ss;
    __syncthreads();
    if (w == 0) {
        int x = warp_sums[lane];
        #pragma unroll
        for (int o = 1; o < 32; o <<= 1) {
            int vv = __shfl_up_sync(0xffffffffu, x, o);
            if (lane >= o) x += vv;
        }
        warp_sums[lane] = x;
    }
    __syncthreads();
    int excl = ((w > 0) ? warp_sums[w - 1] : 0) + ss - s;
    #pragma unroll
    for (int i = 0; i < CH; i++) g_rowptr[base + i] = excl + local[i];
    if (t == 1023) g_rowptr[NN] = warp_sums[31];
}

__global__ void scatter_kernel(const void* __restrict__ ei) {
    int e = blockIdx.x * blockDim.x + threadIdx.x;
    if (e >= ETOT) return;
    int s, d; edge_sd(ei, e, s, d);
    int pos = atomicAdd(&g_cursor[d], 1);
    g_srcs[g_rowptr[d] + pos] = s;
}

// ---------------- GEMM into g_h: g_h[M,256] = A[M,K] @ B[K,256] ----------------
#define BM 128
#define BN 64
#define BK 16
__global__ void gemm_h_kernel(const float* __restrict__ Aext, const float* __restrict__ B,
                              int M, int K, int use_x1) {
    __shared__ float As[BK][BM + 4];
    __shared__ float Bs[BK][BN + 4];
    const float* A = use_x1 ? (const float*)g_x1 : Aext;
    int tid = threadIdx.x;
    int tx = tid & 15, ty = tid >> 4;
    int row0 = blockIdx.y * BM, col0 = blockIdx.x * BN;
    float acc[8][4] = {};
    for (int k0 = 0; k0 < K; k0 += BK) {
        #pragma unroll
        for (int i = 0; i < 8; i++) {
            int idx = tid + i * 256;
            int r = idx >> 4, kk = idx & 15;
            int gr = row0 + r;
            As[kk][r] = (gr < M) ? A[(long)gr * K + k0 + kk] : 0.f;
        }
        #pragma unroll
        for (int i = 0; i < 4; i++) {
            int idx = tid + i * 256;
            int kk = idx >> 6, c = idx & 63;
            Bs[kk][c] = B[(long)(k0 + kk) * HC + col0 + c];
        }
        __syncthreads();
        #pragma unroll
        for (int kk = 0; kk < BK; kk++) {
            float ra[8], rb[4];
            #pragma unroll
            for (int i = 0; i < 8; i++) ra[i] = As[kk][ty * 8 + i];
            #pragma unroll
            for (int j = 0; j < 4; j++) rb[j] = Bs[kk][tx * 4 + j];
            #pragma unroll
            for (int i = 0; i < 8; i++)
                #pragma unroll
                for (int j = 0; j < 4; j++)
                    acc[i][j] += ra[i] * rb[j];
        }
        __syncthreads();
    }
    #pragma unroll
    for (int i = 0; i < 8; i++) {
        int r = row0 + ty * 8 + i;
        if (r < M) {
            float4 v = make_float4(acc[i][0], acc[i][1], acc[i][2], acc[i][3]);
            *(float4*)&g_h[(long)r * HC + col0 + tx * 4] = v;
        }
    }
}

// ---------------- per-node att_l / att_r dots (vectorized) ----------------
__global__ void alr_kernel(const float* __restrict__ att_l, const float* __restrict__ att_r) {
    int warp = (blockIdx.x * blockDim.x + threadIdx.x) >> 5;
    int lane = threadIdx.x & 31;
    if (warp >= NN) return;
    const float4* hv = (const float4*)(g_h + (long)warp * HC);
    const float4* al = (const float4*)att_l;
    const float4* ar = (const float4*)att_r;
    float4 h0 = hv[2 * lane], h1 = hv[2 * lane + 1];
    float4 l0 = al[2 * lane], l1 = al[2 * lane + 1];
    float4 r0 = ar[2 * lane], r1 = ar[2 * lane + 1];
    float dl = h0.x * l0.x + h0.y * l0.y + h0.z * l0.z + h0.w * l0.w
             + h1.x * l1.x + h1.y * l1.y + h1.z * l1.z + h1.w * l1.w;
    float dr = h0.x * r0.x + h0.y * r0.y + h0.z * r0.z + h0.w * r0.w
             + h1.x * r1.x + h1.y * r1.y + h1.z * r1.z + h1.w * r1.w;
    dl += __shfl_xor_sync(0xffffffffu, dl, 1);
    dl += __shfl_xor_sync(0xffffffffu, dl, 2);
    dr += __shfl_xor_sync(0xffffffffu, dr, 1);
    dr += __shfl_xor_sync(0xffffffffu, dr, 2);
    if ((lane & 3) == 0) {
        int h = lane >> 2;
        g_al[warp * HEADS + h] = dl;
        g_ar[warp * HEADS + h] = dr;
    }
}

// ---------------- fused attention + aggregation (online softmax) ----------------
// Block = 256 threads (8 warps), one dst node per block. Each warp owns a
// disjoint subset of in-edges and maintains per-head running (m, den) plus an
// 8-col acc per lane, rescaling on max updates (flash-attention recurrence).
// Lane l owns columns [8l, 8l+8) -> head l>>2; 2 butterfly shuffles give the
// full per-head 32-dim dot to all 4 lanes of the group.
// mode 1: elu -> g_x1 ; mode 0: raw -> g_out2
__global__ void fused_attn_kernel(const float* __restrict__ bias, int mode) {
    int v = blockIdx.x;
    int tid = threadIdx.x;
    int lane = tid & 31;
    int w = tid >> 5;
    int hd = lane >> 2;
    __shared__ float sh_hd[HC];
    __shared__ float sh_m[8][8];
    __shared__ float sh_den[8][8];
    __shared__ float sh_acc[8][HC];
    if (tid < 64)
        ((float4*)sh_hd)[tid] = ((const float4*)(g_h + (long)v * HC))[tid];
    __syncthreads();
    float4 d0 = ((const float4*)sh_hd)[2 * lane];
    float4 d1 = ((const float4*)sh_hd)[2 * lane + 1];
    float ar_d = g_ar[v * HEADS + hd];
    int start = g_rowptr[v], end = g_rowptr[v + 1];
    float m = -INFINITY, den = 0.f;
    float acc[8] = {};
    for (int i = start + w; i < end; i += 8) {
        int s = g_srcs[i];
        const float4* hs = (const float4*)(g_h + (long)s * HC);
        float4 a0 = hs[2 * lane], a1 = hs[2 * lane + 1];
        float dot = a0.x * d0.x + a0.y * d0.y + a0.z * d0.z + a0.w * d0.w
                  + a1.x * d1.x + a1.y * d1.y + a1.z * d1.z + a1.w * d1.w;
        dot += __shfl_xor_sync(0xffffffffu, dot, 1);
        dot += __shfl_xor_sync(0xffffffffu, dot, 2);
        float alpha = (g_al[s * HEADS + hd] + ar_d) * (1.f / (1.f + __expf(-dot)));
        alpha = alpha > 0.f ? alpha : 0.2f * alpha;
        float m_new = fmaxf(m, alpha);
        float c = __expf(m - m_new);
        float p = __expf(alpha - m_new);
        acc[0] = acc[0] * c + a0.x * p;
        acc[1] = acc[1] * c + a0.y * p;
        acc[2] = acc[2] * c + a0.z * p;
        acc[3] = acc[3] * c + a0.w * p;
        acc[4] = acc[4] * c + a1.x * p;
        acc[5] = acc[5] * c + a1.y * p;
        acc[6] = acc[6] * c + a1.z * p;
        acc[7] = acc[7] * c + a1.w * p;
        den = den * c + p;
        m = m_new;
    }
    if ((lane & 3) == 0) { sh_m[w][hd] = m; sh_den[w][hd] = den; }
    float* dstp = &sh_acc[w][8 * lane];
    ((float4*)dstp)[0] = make_float4(acc[0], acc[1], acc[2], acc[3]);
    ((float4*)dstp)[1] = make_float4(acc[4], acc[5], acc[6], acc[7]);
    __syncthreads();
    // thread t finalizes column t (head t>>5)
    int ht = tid >> 5;
    float mf = -INFINITY;
    #pragma unroll
    for (int ww = 0; ww < 8; ww++) mf = fmaxf(mf, sh_m[ww][ht]);
    float accf = 0.f, denf = 0.f;
    #pragma unroll
    for (int ww = 0; ww < 8; ww++) {
        float sc = __expf(sh_m[ww][ht] - mf);
        accf += sh_acc[ww][tid] * sc;
        denf += sh_den[ww][ht] * sc;
    }
    float r = accf / (denf + 1e-16f) + bias[tid];
    if (mode) {
        r = r > 0.f ? r : expm1f(r);
        g_x1[(long)v * HC + tid] = r;
    } else {
        g_out2[(long)v * HC + tid] = r;
    }
}

// ---------------- pooling (sorted batch, binary search) ----------------
__device__ __forceinline__ int lbound_idx(const void* a, int n, int key) {
    int lo = 0, hi = n;
    while (lo < hi) {
        int mid = (lo + hi) >> 1;
        if (idx_at(a, mid) < key) lo = mid + 1; else hi = mid;
    }
    return lo;
}
__global__ void pool_kernel(const void* __restrict__ batch) {
    int g = blockIdx.x;
    int tid = threadIdx.x;
    int lo = lbound_idx(batch, NN, g);
    int hi = lbound_idx(batch, NN, g + 1);
    float acc = 0.f;
    for (int n = lo; n < hi; n++) acc += g_out2[(long)n * HC + tid];
    g_sums[g * HC + tid] = acc;
    if (tid == 0) g_cnt[g] = hi - lo;
}

// ---------------- final linear ----------------
__global__ void final_kernel(const float* __restrict__ linW, const float* __restrict__ linb,
                             float* __restrict__ out) {
    int g = blockIdx.x;
    int tid = threadIdx.x;
    int lane = tid & 31, w = tid >> 5;
    __shared__ float sw[8][CLS];
    float cnt = fmaxf((float)g_cnt[g], 1.f);
    float v = g_sums[g * HC + tid] / cnt;
    #pragma unroll
    for (int c = 0; c < CLS; c++) {
        float t = v * linW[tid * CLS + c];
        #pragma unroll
        for (int o = 16; o; o >>= 1) t += __shfl_xor_sync(0xffffffffu, t, o);
        if (lane == 0) sw[w][c] = t;
    }
    __syncthreads();
    if (tid < CLS) {
        float s = 0.f;
        #pragma unroll
        for (int ww = 0; ww < 8; ww++) s += sw[ww][tid];
        out[g * CLS + tid] = s + linb[tid];
    }
}

// ---------------- launch ----------------
extern "C" void kernel_launch(void* const* d_in, const int* in_sizes, int n_in,
                              void* d_out, int out_size) {
    const float* x = nullptr;
    const void*  ei = nullptr;
    const void*  batch = nullptr;
    const float *W1 = nullptr, *W2 = nullptr, *linW = nullptr, *linb = nullptr;
    const float* p256[6] = {};
    int n256 = 0;
    for (int i = 0; i < n_in; i++) {
        switch (in_sizes[i]) {
            case NN * FIN: x    = (const float*)d_in[i]; break;
            case 2 * EE:   ei   = d_in[i];               break;
            case NN:       batch = d_in[i];              break;
            case FIN * HC: W1   = (const float*)d_in[i]; break;
            case HC * HC:  W2   = (const float*)d_in[i]; break;
            case HC * CLS: linW = (const float*)d_in[i]; break;
            case CLS:      linb = (const float*)d_in[i]; break;
            case HC:       if (n256 < 6) p256[n256++] = (const float*)d_in[i]; break;
            default: break;
        }
    }
    const float* att_l1 = p256[0];
    const float* att_r1 = p256[1];
    const float* b1     = p256[2];
    const float* att_l2 = p256[3];
    const float* att_r2 = p256[4];
    const float* b2     = p256[5];
    float* out = (float*)d_out;
    (void)out_size;

    const int T = 256;
    dim3 ggrid(HC / BN, (NN + BM - 1) / BM);

    // CSR build (shared by both layers)
    init_kernel<<<(NN + T - 1) / T, T>>>(ei);
    degree_kernel<<<(ETOT + T - 1) / T, T>>>(ei);
    scan_kernel<<<1, 1024>>>();
    scatter_kernel<<<(ETOT + T - 1) / T, T>>>(ei);

    // ---- layer 1 ----
    gemm_h_kernel<<<ggrid, 256>>>(x, W1, NN, FIN, 0);
    alr_kernel<<<(NN * 32 + T - 1) / T, T>>>(att_l1, att_r1);
    fused_attn_kernel<<<NN, 256>>>(b1, 1);

    // ---- layer 2 ----
    gemm_h_kernel<<<ggrid, 256>>>(nullptr, W2, NN, HC, 1);
    alr_kernel<<<(NN * 32 + T - 1) / T, T>>>(att_l2, att_r2);
    fused_attn_kernel<<<NN, 256>>>(b2, 0);

    // ---- pool + classify ----
    pool_kernel<<<GG, HC>>>(batch);
    final_kernel<<<GG, HC>>>(linW, linb, out);
}

// round 16
// speedup vs baseline: 1.3211x; 1.3211x over previous
#include <cuda_runtime.h>
#include <cuda_bf16.h>
#include <math.h>

#define NN   20000
#define FIN  128
#define HID  32
#define HEADS 8
#define HC   256
#define EE   320000
#define ETOT 340000
#define GG   64
#define CLS  10

// ---------------- scratch (static device globals; no allocation) ----------------
__device__ __align__(16) float g_h[NN * HC];
__device__ __align__(16) float g_x1[NN * HC];
__device__ __align__(16) float g_out2[NN * HC];
__device__ __align__(16) float g_alpha[ETOT * HEADS];  // CSR-slot-ordered raw alpha
__device__ unsigned g_amax[2][NN * HEADS];             // per-layer segment max
__device__ float    g_al[NN * HEADS];
__device__ float    g_ar[NN * HEADS];
__device__ __align__(16) int g_deg[NN];
__device__ int      g_cursor[NN];
__device__ int      g_rowptr[NN + 1];
__device__ int      g_srcs[ETOT];
__device__ int      g_epos[ETOT];                      // edge id -> CSR slot
__device__ float    g_sums[GG * HC];
__device__ int      g_cnt[GG];
__device__ int      g_is64;

// ---------------- helpers ----------------
__device__ __forceinline__ unsigned enc_f(float f) {
    unsigned u = __float_as_uint(f);
    return (u & 0x80000000u) ? ~u : (u | 0x80000000u);
}
__device__ __forceinline__ float dec_f(unsigned k) {
    return (k & 0x80000000u) ? __uint_as_float(k ^ 0x80000000u) : __uint_as_float(~k);
}
__device__ __forceinline__ int idx_at(const void* p, int i) {
    if (g_is64) return (int)((const long long*)p)[i];
    return ((const int*)p)[i];
}
__device__ __forceinline__ void edge_sd(const void* ei, int e, int& s, int& d) {
    if (e < EE) { s = idx_at(ei, e); d = idx_at(ei, EE + e); }
    else        { s = e - EE; d = e - EE; }
}
__device__ __forceinline__ int edge_dst(const void* ei, int e) {
    return (e < EE) ? idx_at(ei, EE + e) : (e - EE);
}

// ---------------- init: zero deg/cursor + both amax layers + dtype detect ----------------
__global__ void init_kernel(const void* ei) {
    int i = blockIdx.x * blockDim.x + threadIdx.x;
    if (i < NN) { g_deg[i] = 0; g_cursor[i] = 0; }
    if (i < NN * HEADS) { g_amax[0][i] = 0u; g_amax[1][i] = 0u; }
    if (i == 0) {
        const int* p = (const int*)ei;
        int or_hi = 0;
        #pragma unroll
        for (int k = 0; k < 64; k++) or_hi |= p[2 * k + 1];
        g_is64 = (or_hi == 0) ? 1 : 0;
    }
}

// ---------------- CSR build ----------------
__global__ void degree_kernel(const void* __restrict__ ei) {
    int e = blockIdx.x * blockDim.x + threadIdx.x;
    if (e >= ETOT) return;
    atomicAdd(&g_deg[edge_dst(ei, e)], 1);
}

// shfl-based scan: 1024 threads x 20 items, int4 loads
__global__ void scan_kernel() {
    __shared__ int warp_sums[32];
    const int CH = 20;
    int t = threadIdx.x;
    int lane = t & 31, w = t >> 5;
    int base = t * CH;
    int local[CH];
    #pragma unroll
    for (int i = 0; i < CH / 4; i++) {
        int4 v4 = ((const int4*)g_deg)[(base >> 2) + i];
        local[4 * i + 0] = v4.x; local[4 * i + 1] = v4.y;
        local[4 * i + 2] = v4.z; local[4 * i + 3] = v4.w;
    }
    int s = 0;
    #pragma unroll
    for (int i = 0; i < CH; i++) { int v = local[i]; local[i] = s; s += v; }
    int ss = s;
    #pragma unroll
    for (int o = 1; o < 32; o <<= 1) {
        int vv = __shfl_up_sync(0xffffffffu, ss, o);
        if (lane >= o) ss += vv;
    }
    if (lane == 31) warp_sums[w] = ss;
    __syncthreads();
    if (w == 0) {
        int x = warp_sums[lane];
        #pragma unroll
        for (int o = 1; o < 32; o <<= 1) {
            int vv = __shfl_up_sync(0xffffffffu, x, o);
            if (lane >= o) x += vv;
        }
        warp_sums[lane] = x;
    }
    __syncthreads();
    int excl = ((w > 0) ? warp_sums[w - 1] : 0) + ss - s;
    #pragma unroll
    for (int i = 0; i < CH; i++) g_rowptr[base + i] = excl + local[i];
    if (t == 1023) g_rowptr[NN] = warp_sums[31];
}

__global__ void scatter_kernel(const void* __restrict__ ei) {
    int e = blockIdx.x * blockDim.x + threadIdx.x;
    if (e >= ETOT) return;
    int s, d; edge_sd(ei, e, s, d);
    int pos = atomicAdd(&g_cursor[d], 1);
    int slot = g_rowptr[d] + pos;
    g_srcs[slot] = s;
    g_epos[e] = slot;
}

// ---------------- GEMM into g_h: g_h[M,256] = A[M,K] @ B[K,256] ----------------
// 128x64 tile, 256 threads, 8x4 acc, register-prefetch pipeline, float4 LDG.
#define BM 128
#define BN 64
#define BK 16
__global__ void gemm_h_kernel(const float* __restrict__ Aext, const float* __restrict__ B,
                              int M, int K, int use_x1) {
    __shared__ float As[BK][BM + 4];
    __shared__ float Bs[BK][BN + 4];
    const float* A = use_x1 ? (const float*)g_x1 : Aext;
    int tid = threadIdx.x;
    int tx = tid & 15, ty = tid >> 4;
    int row0 = blockIdx.y * BM, col0 = blockIdx.x * BN;
    // A: 128x16 = 512 float4; thread loads 2. B: 16x64 = 256 float4; thread loads 1.
    int aq0 = tid, aq1 = tid + 256;
    int ar0 = aq0 >> 2, ak0 = aq0 & 3;
    int ar1 = aq1 >> 2, ak1 = aq1 & 3;
    int bk = tid >> 4, bc = tid & 15;
    float4 a_reg0, a_reg1, b_reg;
    // prologue: load tile 0
    {
        int gr0 = row0 + ar0, gr1 = row0 + ar1;
        a_reg0 = (gr0 < M) ? *(const float4*)&A[(long)gr0 * K + 4 * ak0]
                           : make_float4(0.f, 0.f, 0.f, 0.f);
        a_reg1 = (gr1 < M) ? *(const float4*)&A[(long)gr1 * K + 4 * ak1]
                           : make_float4(0.f, 0.f, 0.f, 0.f);
        b_reg = *(const float4*)&B[(long)bk * HC + col0 + 4 * bc];
    }
    float acc[8][4] = {};
    for (int k0 = 0; k0 < K; k0 += BK) {
        // commit staged regs to smem
        As[4 * ak0 + 0][ar0] = a_reg0.x; As[4 * ak0 + 1][ar0] = a_reg0.y;
        As[4 * ak0 + 2][ar0] = a_reg0.z; As[4 * ak0 + 3][ar0] = a_reg0.w;
        As[4 * ak1 + 0][ar1] = a_reg1.x; As[4 * ak1 + 1][ar1] = a_reg1.y;
        As[4 * ak1 + 2][ar1] = a_reg1.z; As[4 * ak1 + 3][ar1] = a_reg1.w;
        *(float4*)&Bs[bk][4 * bc] = b_reg;
        __syncthreads();
        // prefetch next tile into registers (overlaps with FFMA below)
        int k1 = k0 + BK;
        if (k1 < K) {
            int gr0 = row0 + ar0, gr1 = row0 + ar1;
            a_reg0 = (gr0 < M) ? *(const float4*)&A[(long)gr0 * K + k1 + 4 * ak0]
                               : make_float4(0.f, 0.f, 0.f, 0.f);
            a_reg1 = (gr1 < M) ? *(const float4*)&A[(long)gr1 * K + k1 + 4 * ak1]
                               : make_float4(0.f, 0.f, 0.f, 0.f);
            b_reg = *(const float4*)&B[(long)(k1 + bk) * HC + col0 + 4 * bc];
        }
        #pragma unroll
        for (int kk = 0; kk < BK; kk++) {
            float ra[8], rb[4];
            #pragma unroll
            for (int i = 0; i < 8; i++) ra[i] = As[kk][ty * 8 + i];
            #pragma unroll
            for (int j = 0; j < 4; j++) rb[j] = Bs[kk][tx * 4 + j];
            #pragma unroll
            for (int i = 0; i < 8; i++)
                #pragma unroll
                for (int j = 0; j < 4; j++)
                    acc[i][j] += ra[i] * rb[j];
        }
        __syncthreads();
    }
    #pragma unroll
    for (int i = 0; i < 8; i++) {
        int r = row0 + ty * 8 + i;
        if (r < M) {
            float4 v = make_float4(acc[i][0], acc[i][1], acc[i][2], acc[i][3]);
            *(float4*)&g_h[(long)r * HC + col0 + tx * 4] = v;
        }
    }
}

// ---------------- per-node att_l / att_r dots (vectorized) ----------------
__global__ void alr_kernel(const float* __restrict__ att_l, const float* __restrict__ att_r) {
    int warp = (blockIdx.x * blockDim.x + threadIdx.x) >> 5;
    int lane = threadIdx.x & 31;
    if (warp >= NN) return;
    const float4* hv = (const float4*)(g_h + (long)warp * HC);
    const float4* al = (const float4*)att_l;
    const float4* ar = (const float4*)att_r;
    float4 h0 = hv[2 * lane], h1 = hv[2 * lane + 1];
    float4 l0 = al[2 * lane], l1 = al[2 * lane + 1];
    float4 r0 = ar[2 * lane], r1 = ar[2 * lane + 1];
    float dl = h0.x * l0.x + h0.y * l0.y + h0.z * l0.z + h0.w * l0.w
             + h1.x * l1.x + h1.y * l1.y + h1.z * l1.z + h1.w * l1.w;
    float dr = h0.x * r0.x + h0.y * r0.y + h0.z * r0.z + h0.w * r0.w
             + h1.x * r1.x + h1.y * r1.y + h1.z * r1.z + h1.w * r1.w;
    dl += __shfl_xor_sync(0xffffffffu, dl, 1);
    dl += __shfl_xor_sync(0xffffffffu, dl, 2);
    dr += __shfl_xor_sync(0xffffffffu, dr, 1);
    dr += __shfl_xor_sync(0xffffffffu, dr, 2);
    if ((lane & 3) == 0) {
        int h = lane >> 2;
        g_al[warp * HEADS + h] = dl;
        g_ar[warp * HEADS + h] = dr;
    }
}

// ---------------- edge alpha: logits dot + alpha + segment max ----------------
// One warp per edge (340k independent warps — latency fully hidden).
// Writes alpha at the edge's CSR slot so aggregate streams it sequentially.
__global__ void edge_alpha_kernel(const void* __restrict__ ei, int layer) {
    int warp = (blockIdx.x * blockDim.x + threadIdx.x) >> 5;
    int lane = threadIdx.x & 31;
    if (warp >= ETOT) return;
    int s, d; edge_sd(ei, warp, s, d);
    int slot = g_epos[warp];
    const float4* hs = (const float4*)(g_h + (long)s * HC);
    const float4* hd = (const float4*)(g_h + (long)d * HC);
    float4 a0 = hs[2 * lane], a1 = hs[2 * lane + 1];
    float4 b0 = hd[2 * lane], b1 = hd[2 * lane + 1];
    float dot = a0.x * b0.x + a0.y * b0.y + a0.z * b0.z + a0.w * b0.w
              + a1.x * b1.x + a1.y * b1.y + a1.z * b1.z + a1.w * b1.w;
    dot += __shfl_xor_sync(0xffffffffu, dot, 1);
    dot += __shfl_xor_sync(0xffffffffu, dot, 2);
    if ((lane & 3) == 0) {
        int h = lane >> 2;
        float a = g_al[s * HEADS + h] + g_ar[d * HEADS + h];
        float sg = 1.f / (1.f + __expf(-dot));
        a *= sg;
        a = a > 0.f ? a : 0.2f * a;
        g_alpha[slot * HEADS + h] = a;
        atomicMax(&g_amax[layer][d * HEADS + h], enc_f(a));
    }
}

// ---------------- aggregation with inline softmax denominator ----------------
// Block per dst, 256 threads. Sequential CSR reads of srcs+alpha; unroll-4
// independent accumulators for MLP. exp per warp is duplicated across lanes
// (free: MUFU cost is per warp-instruction).
__global__ void aggregate_kernel(const float* __restrict__ b, int layer, int mode) {
    int v = blockIdx.x;
    int tid = threadIdx.x;
    int hh = tid >> 5;
    float amax = dec_f(g_amax[layer][v * HEADS + hh]);
    int i = g_rowptr[v], end = g_rowptr[v + 1];
    float acc0 = 0.f, acc1 = 0.f, acc2 = 0.f, acc3 = 0.f, den = 0.f;
    for (; i + 3 < end; i += 4) {
        int s0 = g_srcs[i], s1 = g_srcs[i + 1], s2 = g_srcs[i + 2], s3 = g_srcs[i + 3];
        float w0 = __expf(g_alpha[(i)     * HEADS + hh] - amax);
        float w1 = __expf(g_alpha[(i + 1) * HEADS + hh] - amax);
        float w2 = __expf(g_alpha[(i + 2) * HEADS + hh] - amax);
        float w3 = __expf(g_alpha[(i + 3) * HEADS + hh] - amax);
        acc0 += g_h[(long)s0 * HC + tid] * w0;
        acc1 += g_h[(long)s1 * HC + tid] * w1;
        acc2 += g_h[(long)s2 * HC + tid] * w2;
        acc3 += g_h[(long)s3 * HC + tid] * w3;
        den += (w0 + w1) + (w2 + w3);
    }
    for (; i < end; i++) {
        int s0 = g_srcs[i];
        float w0 = __expf(g_alpha[(i) * HEADS + hh] - amax);
        acc0 += g_h[(long)s0 * HC + tid] * w0;
        den += w0;
    }
    float r = ((acc0 + acc1) + (acc2 + acc3)) / (den + 1e-16f) + b[tid];
    if (mode) {
        r = r > 0.f ? r : expm1f(r);
        g_x1[(long)v * HC + tid] = r;
    } else {
        g_out2[(long)v * HC + tid] = r;
    }
}

// ---------------- pooling (sorted batch, binary search) ----------------
__device__ __forceinline__ int lbound_idx(const void* a, int n, int key) {
    int lo = 0, hi = n;
    while (lo < hi) {
        int mid = (lo + hi) >> 1;
        if (idx_at(a, mid) < key) lo = mid + 1; else hi = mid;
    }
    return lo;
}
__global__ void pool_kernel(const void* __restrict__ batch) {
    int g = blockIdx.x;
    int tid = threadIdx.x;
    int lo = lbound_idx(batch, NN, g);
    int hi = lbound_idx(batch, NN, g + 1);
    float acc = 0.f;
    for (int n = lo; n < hi; n++) acc += g_out2[(long)n * HC + tid];
    g_sums[g * HC + tid] = acc;
    if (tid == 0) g_cnt[g] = hi - lo;
}

// ---------------- final linear ----------------
__global__ void final_kernel(const float* __restrict__ linW, const float* __restrict__ linb,
                             float* __restrict__ out) {
    int g = blockIdx.x;
    int tid = threadIdx.x;
    int lane = tid & 31, w = tid >> 5;
    __shared__ float sw[8][CLS];
    float cnt = fmaxf((float)g_cnt[g], 1.f);
    float v = g_sums[g * HC + tid] / cnt;
    #pragma unroll
    for (int c = 0; c < CLS; c++) {
        float t = v * linW[tid * CLS + c];
        #pragma unroll
        for (int o = 16; o; o >>= 1) t += __shfl_xor_sync(0xffffffffu, t, o);
        if (lane == 0) sw[w][c] = t;
    }
    __syncthreads();
    if (tid < CLS) {
        float s = 0.f;
        #pragma unroll
        for (int ww = 0; ww < 8; ww++) s += sw[ww][tid];
        out[g * CLS + tid] = s + linb[tid];
    }
}

// ---------------- launch ----------------
extern "C" void kernel_launch(void* const* d_in, const int* in_sizes, int n_in,
                              void* d_out, int out_size) {
    const float* x = nullptr;
    const void*  ei = nullptr;
    const void*  batch = nullptr;
    const float *W1 = nullptr, *W2 = nullptr, *linW = nullptr, *linb = nullptr;
    const float* p256[6] = {};
    int n256 = 0;
    for (int i = 0; i < n_in; i++) {
        switch (in_sizes[i]) {
            case NN * FIN: x    = (const float*)d_in[i]; break;
            case 2 * EE:   ei   = d_in[i];               break;
            case NN:       batch = d_in[i];              break;
            case FIN * HC: W1   = (const float*)d_in[i]; break;
            case HC * HC:  W2   = (const float*)d_in[i]; break;
            case HC * CLS: linW = (const float*)d_in[i]; break;
            case CLS:      linb = (const float*)d_in[i]; break;
            case HC:       if (n256 < 6) p256[n256++] = (const float*)d_in[i]; break;
            default: break;
        }
    }
    const float* att_l1 = p256[0];
    const float* att_r1 = p256[1];
    const float* b1     = p256[2];
    const float* att_l2 = p256[3];
    const float* att_r2 = p256[4];
    const float* b2     = p256[5];
    float* out = (float*)d_out;
    (void)out_size;

    const int T = 256;
    dim3 ggrid(HC / BN, (NN + BM - 1) / BM);

    // CSR build (shared by both layers) + init
    init_kernel<<<(NN * HEADS + T - 1) / T, T>>>(ei);
    degree_kernel<<<(ETOT + T - 1) / T, T>>>(ei);
    scan_kernel<<<1, 1024>>>();
    scatter_kernel<<<(ETOT + T - 1) / T, T>>>(ei);

    // ---- layer 1 ----
    gemm_h_kernel<<<ggrid, 256>>>(x, W1, NN, FIN, 0);
    alr_kernel<<<(NN * 32 + T - 1) / T, T>>>(att_l1, att_r1);
    edge_alpha_kernel<<<(ETOT * 32 + T - 1) / T, T>>>(ei, 0);
    aggregate_kernel<<<NN, 256>>>(b1, 0, 1);

    // ---- layer 2 ----
    gemm_h_kernel<<<ggrid, 256>>>(nullptr, W2, NN, HC, 1);
    alr_kernel<<<(NN * 32 + T - 1) / T, T>>>(att_l2, att_r2);
    edge_alpha_kernel<<<(ETOT * 32 + T - 1) / T, T>>>(ei, 1);
    aggregate_kernel<<<NN, 256>>>(b2, 1, 0);

    // ---- pool + classify ----
    pool_kernel<<<GG, HC>>>(batch);
    final_kernel<<<GG, HC>>>(linW, linb, out);
}